// round 3
// baseline (speedup 1.0000x reference)
#include <cuda_runtime.h>

// ============================================================================
// RGNN recurrent graph-polynomial filter, fp32 SIMT GEMM implementation.
//   h_t = relu( sum_k L^{k+1} (x_t W_k + h_{t-1} H_k) )
// B=8, T=16, N=1024, F=128, K=4.
//
// Decomposition (all GEMMs, all dims multiples of 128 -> no bounds checks):
//   Lcat[n][k*1024+m] = (L^{k+1})[n][m]                       (3 power GEMMs)
//   g_WH[f][k*128+g] = W[k][f][g] ; g_WH[128+f][..] = H[k][f][g]
//   per t:
//     S[k*1024+n][b*128+g] = sum_f x[b,t,n,f] Wcat + h[b,n,f] Hcat
//         -> one 8192 x 512 x 256 GEMM (A = [x_t | h] virtual concat)
//     Cpart[s] = Lcat[:, s-chunk] @ S[s-chunk, :]  (split-K=4, 1024x1024x1024)
//     h/out    = relu(sum_s Cpart[s])              (reduce kernel)
// ============================================================================

__device__ float g_Lcat[1024u * 4096u];       // 16 MB  [n][k*1024+m]
__device__ float g_S[4096u * 1024u];          // 16 MB  [k*1024+m][b*128+g]
__device__ float g_h[8192u * 128u];           //  4 MB  [(b*1024+n)][f]
__device__ float g_Cpart[4u * 1024u * 1024u]; // 16 MB  [s][n][b*128+g]
__device__ float g_WH[256u * 512u];           // 512 KB [f | 128+f][k*128+g]

// ----------------------------------------------------------------------------
// Generic 128x128 SGEMM tile, BK=8, 256 threads, 8x8 micro-tile per thread,
// register-prefetch + shared-memory double buffering.
// MODE 10: powers.  A = g_Lcat + off (lda 4096), B = ext (L, ldb 1024),
//          split-K=4 (chunk 256) -> g_Cpart.
// MODE 11: main.    A = g_Lcat (lda 4096), B = g_S (ldb 1024),
//          split-K=4 (chunk 1024) -> g_Cpart.
// MODE  2: feature. A = [x_t | h] (K=256, switch at k=128), B = g_WH (ldb 512),
//          scatter-store into g_S.
// ----------------------------------------------------------------------------
template<int MODE>
__global__ __launch_bounds__(256, 2)
void sgemm_k(const float* __restrict__ ext, int off)
{
    constexpr int KI   = (MODE == 11) ? 128 : 32;                 // k-tiles of 8
    constexpr int CHNK = (MODE == 11) ? 1024 : (MODE == 10 ? 256 : 0);

    __shared__ float As[2][8][132];   // [buf][k][m], padded: conflict-free STS
    __shared__ float Bs[2][8][128];   // [buf][k][n]

    const int tid      = threadIdx.x;
    const int blockRow = blockIdx.y << 7;
    const int blockCol = blockIdx.x << 7;
    const int kOffset  = blockIdx.z * CHNK;

    // global->smem load mapping: one float4 per thread per tile for A and B
    const int aRow  = tid >> 1;          // 0..127
    const int aCol4 = (tid & 1) << 2;    // 0 or 4
    const int bRow  = tid >> 5;          // 0..7
    const int bCol4 = (tid & 31) << 2;   // 0..124

    const float* aP0;
    const float* aP1 = nullptr;
    {
        const int gRow = blockRow + aRow;
        if (MODE == 2) {
            // rows are (b, n); x strides: b: T*N*F = 2097152, t: 131072, n: 128
            const int b = gRow >> 10, n = gRow & 1023;
            aP0 = ext + (size_t)b * 2097152u + (size_t)off + (size_t)n * 128 + aCol4;
            aP1 = g_h + (size_t)gRow * 128 + aCol4;
        } else if (MODE == 10) {
            aP0 = g_Lcat + (size_t)off + (size_t)gRow * 4096 + kOffset + aCol4;
        } else {
            aP0 = g_Lcat + (size_t)gRow * 4096 + kOffset + aCol4;
        }
    }
    const float* bP;
    size_t ldb8;
    if (MODE == 2)       { bP = g_WH + (size_t)bRow * 512 + blockCol + bCol4;              ldb8 = 8 * 512; }
    else if (MODE == 10) { bP = ext  + (size_t)(kOffset + bRow) * 1024 + blockCol + bCol4; ldb8 = 8 * 1024; }
    else                 { bP = g_S  + (size_t)(kOffset + bRow) * 1024 + blockCol + bCol4; ldb8 = 8 * 1024; }

    // compute mapping: thread (tx, ty) owns rows {ty*4..+3, 64+ty*4..+3} x
    // cols {tx*4..+3, 64+tx*4..+3} -> conflict-free LDS.128 on both operands
    const int tx = tid & 15, ty = tid >> 4;

    float acc[8][8];
#pragma unroll
    for (int i = 0; i < 8; ++i)
#pragma unroll
        for (int j = 0; j < 8; ++j) acc[i][j] = 0.0f;

    // fetch tile 0 (for MODE 2, iteration 0 is always in the x half)
    float4 aReg = *(const float4*)aP0;
    float4 bReg = *(const float4*)bP;

    As[0][aCol4 + 0][aRow] = aReg.x;
    As[0][aCol4 + 1][aRow] = aReg.y;
    As[0][aCol4 + 2][aRow] = aReg.z;
    As[0][aCol4 + 3][aRow] = aReg.w;
    *(float4*)&Bs[0][bRow][bCol4] = bReg;
    __syncthreads();

    int buf = 0;
    for (int it = 0; it < KI; ++it) {
        const bool has = (it + 1 < KI);
        if (has) {
            const int nx = it + 1;
            if (MODE == 2) {
                aReg = (nx < 16) ? *(const float4*)(aP0 + nx * 8)
                                 : *(const float4*)(aP1 + (nx - 16) * 8);
            } else {
                aReg = *(const float4*)(aP0 + nx * 8);
            }
            bReg = *(const float4*)(bP + (size_t)nx * ldb8);
        }
#pragma unroll
        for (int k = 0; k < 8; ++k) {
            float ar[8], br[8];
            *(float4*)&ar[0] = *(const float4*)&As[buf][k][ty * 4];
            *(float4*)&ar[4] = *(const float4*)&As[buf][k][64 + ty * 4];
            *(float4*)&br[0] = *(const float4*)&Bs[buf][k][tx * 4];
            *(float4*)&br[4] = *(const float4*)&Bs[buf][k][64 + tx * 4];
#pragma unroll
            for (int i = 0; i < 8; ++i)
#pragma unroll
                for (int j = 0; j < 8; ++j)
                    acc[i][j] = fmaf(ar[i], br[j], acc[i][j]);
        }
        if (has) {
            buf ^= 1;
            As[buf][aCol4 + 0][aRow] = aReg.x;
            As[buf][aCol4 + 1][aRow] = aReg.y;
            As[buf][aCol4 + 2][aRow] = aReg.z;
            As[buf][aCol4 + 3][aRow] = aReg.w;
            *(float4*)&Bs[buf][bRow][bCol4] = bReg;
            __syncthreads();
        }
    }

    // epilogue
#pragma unroll
    for (int i = 0; i < 8; ++i) {
        const int r = blockRow + ((i >> 2) * 64) + ty * 4 + (i & 3);
#pragma unroll
        for (int jh = 0; jh < 2; ++jh) {
            const int c = blockCol + jh * 64 + tx * 4;
            const float4 v = make_float4(acc[i][jh * 4 + 0], acc[i][jh * 4 + 1],
                                         acc[i][jh * 4 + 2], acc[i][jh * 4 + 3]);
            if (MODE == 2) {
                // row r = (b, n); col c = (k, g) -> S[(k*1024+n)][b*128+g]
                const int b = r >> 10, n = r & 1023;
                const int kk = c >> 7, g = c & 127;
                *(float4*)(g_S + ((size_t)(kk * 1024 + n)) * 1024 + b * 128 + g) = v;
            } else {
                *(float4*)(g_Cpart + (size_t)blockIdx.z * (1024u * 1024u)
                                   + (size_t)r * 1024 + c) = v;
            }
        }
    }
}

// ---------------------------------------------------------------------------
// small kernels
// ---------------------------------------------------------------------------
__global__ void zero_h_k()
{
    const size_t e = ((size_t)blockIdx.x * 256 + threadIdx.x) * 4;
    *(float4*)(g_h + e) = make_float4(0.f, 0.f, 0.f, 0.f);
}

__global__ void copyL_k(const float* __restrict__ L)
{
    const size_t e = ((size_t)blockIdx.x * 256 + threadIdx.x) * 4;
    const int n = (int)(e >> 10), m = (int)(e & 1023);
    *(float4*)(g_Lcat + (size_t)n * 4096 + m) = *(const float4*)(L + e);
}

__global__ void catWH_k(const float* __restrict__ W, const float* __restrict__ H)
{
    const int e = (blockIdx.x * 256 + threadIdx.x) * 4; // over K*F*F = 65536
    const int k = e >> 14, f = (e >> 7) & 127, g = e & 127;
    *(float4*)(g_WH + f * 512 + k * 128 + g)         = *(const float4*)(W + e);
    *(float4*)(g_WH + (128 + f) * 512 + k * 128 + g) = *(const float4*)(H + e);
}

__global__ void reduce_pow_k(int kslot)
{
    const size_t e = ((size_t)blockIdx.x * 256 + threadIdx.x) * 4;
    const float4 a = *(const float4*)(g_Cpart + e);
    const float4 b = *(const float4*)(g_Cpart + 1048576u + e);
    const float4 c = *(const float4*)(g_Cpart + 2097152u + e);
    const float4 d = *(const float4*)(g_Cpart + 3145728u + e);
    const float4 s = make_float4(a.x + b.x + c.x + d.x, a.y + b.y + c.y + d.y,
                                 a.z + b.z + c.z + d.z, a.w + b.w + c.w + d.w);
    const int n = (int)(e >> 10), m = (int)(e & 1023);
    *(float4*)(g_Lcat + (size_t)n * 4096 + kslot * 1024 + m) = s;
}

__global__ void reduce_relu_k(float* __restrict__ out, int t)
{
    const size_t e = ((size_t)blockIdx.x * 256 + threadIdx.x) * 4;
    const float4 a = *(const float4*)(g_Cpart + e);
    const float4 b = *(const float4*)(g_Cpart + 1048576u + e);
    const float4 c = *(const float4*)(g_Cpart + 2097152u + e);
    const float4 d = *(const float4*)(g_Cpart + 3145728u + e);
    float4 s = make_float4(a.x + b.x + c.x + d.x, a.y + b.y + c.y + d.y,
                           a.z + b.z + c.z + d.z, a.w + b.w + c.w + d.w);
    s.x = fmaxf(s.x, 0.f); s.y = fmaxf(s.y, 0.f);
    s.z = fmaxf(s.z, 0.f); s.w = fmaxf(s.w, 0.f);
    const int n = (int)(e >> 10);
    const int j = (int)(e & 1023);
    const int bb = j >> 7, g = j & 127;
    *(float4*)(g_h + ((size_t)(bb * 1024 + n)) * 128 + g) = s;
    *(float4*)(out + (((size_t)(bb * 16 + t)) * 1024 + n) * 128 + g) = s;
}

// ---------------------------------------------------------------------------
// launch
// ---------------------------------------------------------------------------
extern "C" void kernel_launch(void* const* d_in, const int* in_sizes, int n_in,
                              void* d_out, int out_size)
{
    const float* x = (const float*)d_in[0]; // [8,16,1024,128]
    const float* L = (const float*)d_in[1]; // [1024,1024]
    const float* W = (const float*)d_in[2]; // [4,128,128]
    const float* H = (const float*)d_in[3]; // [4,128,128]
    float* out = (float*)d_out;             // [8,16,1024,128]

    (void)in_sizes; (void)n_in; (void)out_size;

    zero_h_k<<<1024, 256>>>();
    copyL_k<<<1024, 256>>>(L);
    catWH_k<<<64, 256>>>(W, H);

    // L powers: Lcat slot k = Lcat slot (k-1) @ L   (split-K=4 + reduce)
    for (int k = 1; k < 4; ++k) {
        sgemm_k<10><<<dim3(8, 8, 4), 256>>>(L, (k - 1) * 1024);
        reduce_pow_k<<<1024, 256>>>(k);
    }

    // recurrence
    for (int t = 0; t < 16; ++t) {
        sgemm_k<2><<<dim3(4, 64, 1), 256>>>(x, t * 131072);   // S = [x_t|h] @ [W;H]
        sgemm_k<11><<<dim3(8, 8, 4), 256>>>(nullptr, 0);       // Cpart = Lcat @ S
        reduce_relu_k<<<1024, 256>>>(out, t);                  // h, out = relu(sum)
    }
}

// round 5
// speedup vs baseline: 1.8002x; 1.8002x over previous
#include <cuda_runtime.h>
#include <cuda_bf16.h>
#include <cstdint>

// ============================================================================
// RGNN via warp-level mma.sync (bf16x3 split precision), sm_100-compatible.
//   h_t = relu( sum_k L^{k+1} (x_t W_k + h_{t-1} H_k) ), B=8,T=16,N=1024,F=128,K=4
//
// fp32 value v = hi(bf16) + lo(bf16 residual); C ~= AhBh + AhBl + AlBh.
//
//   MODE 2 (powers):  Lslot[s] = Lslot[s-1] @ L      (B = L^T hi/lo, K=1024)
//   MODE 1 (feature): D[(k,g)][(b,m)] = WHT @ [x_t|h]           (K=256)
//   MODE 0 (main):    z[m][(b,g)]     = Lcat @ St^T             (K=4096)
// ============================================================================

// ---------------- device globals ----------------
__device__ __align__(256) __nv_bfloat16 g_Lh  [1024u * 4096u]; // L^1..L^4 hi [m][k]
__device__ __align__(256) __nv_bfloat16 g_Ll  [1024u * 4096u]; // lo
__device__ __align__(256) __nv_bfloat16 g_LTh [1024u * 1024u]; // L^T hi [n][k]
__device__ __align__(256) __nv_bfloat16 g_LTl [1024u * 1024u];
__device__ __align__(256) __nv_bfloat16 g_Sth [1024u * 4096u]; // St hi [(b,g)][(k,m)]
__device__ __align__(256) __nv_bfloat16 g_Stl [1024u * 4096u];
__device__ __align__(256) __nv_bfloat16 g_xh  [16777216u];     // x hi [b][t][n][f]
__device__ __align__(256) __nv_bfloat16 g_xl  [16777216u];
__device__ __align__(256) __nv_bfloat16 g_hh  [1048576u];      // h hi [(b*1024+n)][f]
__device__ __align__(256) __nv_bfloat16 g_hl  [1048576u];
__device__ __align__(256) __nv_bfloat16 g_WHTh[512u * 256u];   // WHT hi [(k*128+g)][f']
__device__ __align__(256) __nv_bfloat16 g_WHTl[512u * 256u];

// ---------------- helpers ----------------
__device__ __forceinline__ uint32_t smem_u32(const void* p) {
    uint32_t a;
    asm("{ .reg .u64 t; cvta.to.shared.u64 t, %1; cvt.u32.u64 %0, t; }"
        : "=r"(a) : "l"(p));
    return a;
}
__device__ __forceinline__ void cp16(uint32_t dst, const void* src) {
    asm volatile("cp.async.cg.shared.global [%0], [%1], 16;" :: "r"(dst), "l"(src));
}
__device__ __forceinline__ void ldm4(uint32_t* r, uint32_t a) {
    asm volatile("ldmatrix.sync.aligned.m8n8.x4.shared.b16 {%0,%1,%2,%3}, [%4];"
        : "=r"(r[0]), "=r"(r[1]), "=r"(r[2]), "=r"(r[3]) : "r"(a));
}
__device__ __forceinline__ void mma16816(float* d, const uint32_t* a, const uint32_t* b) {
    asm volatile(
        "mma.sync.aligned.m16n8k16.row.col.f32.bf16.bf16.f32 "
        "{%0,%1,%2,%3}, {%4,%5,%6,%7}, {%8,%9}, {%0,%1,%2,%3};"
        : "+f"(d[0]), "+f"(d[1]), "+f"(d[2]), "+f"(d[3])
        : "r"(a[0]), "r"(a[1]), "r"(a[2]), "r"(a[3]), "r"(b[0]), "r"(b[1]));
}
__device__ __forceinline__ void split2(float v, __nv_bfloat16& h, __nv_bfloat16& l) {
    h = __float2bfloat16(v);
    l = __float2bfloat16(v - __bfloat162float(h));
}

// ---------------- smem geometry ----------------
// 32 bf16 per row = 64B data + 16B pad -> pitch 80B: ldmatrix rows hit
// distinct bank groups (0,20,8,28,16,4,24,12 word-banks), cp.async conflict-free.
static constexpr int PITCH    = 80;
static constexpr int A_BYTES  = 128 * PITCH;             // 10240
static constexpr int B_BYTES  = 64 * PITCH;              // 5120
static constexpr int BUF_B    = 2 * A_BYTES + 2 * B_BYTES; // 30720
static constexpr int SMEM_TOT = 2 * BUF_B;               // 61440

// ============================================================================
// Unified GEMM kernel. CTA tile 128(m) x 64(n), 8 warps of 32x32, k-chunk 32.
// MODE 0: main  (K=4096)  MODE 1: feature (K=256)  MODE 2: powers (K=1024)
// ============================================================================
template<int MODE>
__global__ __launch_bounds__(256, 2)
void mma_k(float* __restrict__ out, const int targ)   // targ = t (0,1) or slot (2)
{
    extern __shared__ __align__(128) char sm[];
    const uint32_t smb = smem_u32(sm);
    const int tid  = threadIdx.x;
    const int wid  = tid >> 5, lane = tid & 31;
    const int row0 = blockIdx.y * 128;
    const int n0   = blockIdx.x * 64;

    constexpr int NCH = (MODE == 0) ? 128 : (MODE == 1 ? 8 : 32);

    const __nv_bfloat16 *Ah, *Al;
    int lda;
    if (MODE == 1) {
        Ah = g_WHTh + (size_t)row0 * 256; Al = g_WHTl + (size_t)row0 * 256; lda = 256;
    } else {
        const int kofs = (MODE == 2) ? (targ - 1) * 1024 : 0;
        Ah = g_Lh + (size_t)row0 * 4096 + kofs;
        Al = g_Ll + (size_t)row0 * 4096 + kofs;
        lda = 4096;
    }

    auto load_chunk = [&](int buf, int ch) {
        const int k0 = ch * 32;
        const uint32_t base = smb + buf * BUF_B;
        // A: 128 rows x 32 bf16, hi+lo -> 4 cp.async/thread
#pragma unroll
        for (int i = 0; i < 2; ++i) {
            const int idx = i * 256 + tid;          // 0..511
            const int r = idx >> 2, c16 = idx & 3;
            const size_t o = (size_t)r * lda + k0 + c16 * 8;
            const uint32_t d = base + r * PITCH + c16 * 16;
            cp16(d,           Ah + o);
            cp16(d + A_BYTES, Al + o);
        }
        // B: 64 rows x 32 bf16, hi+lo -> 2 cp.async/thread
        {
            const int r = tid >> 2, c16 = tid & 3;
            const __nv_bfloat16 *sh, *sl;
            if (MODE == 0) {
                const size_t o = (size_t)(n0 + r) * 4096 + k0 + c16 * 8;
                sh = g_Sth + o; sl = g_Stl + o;
            } else if (MODE == 2) {
                const size_t o = (size_t)(n0 + r) * 1024 + k0 + c16 * 8;
                sh = g_LTh + o; sl = g_LTl + o;
            } else {
                const int j = n0 + r, b = j >> 10, m = j & 1023;
                if (k0 < 128) {
                    const size_t o = (((size_t)(b * 16 + targ)) * 1024 + m) * 128
                                   + k0 + c16 * 8;
                    sh = g_xh + o; sl = g_xl + o;
                } else {
                    const size_t o = ((size_t)(b * 1024 + m)) * 128
                                   + (k0 - 128) + c16 * 8;
                    sh = g_hh + o; sl = g_hl + o;
                }
            }
            const uint32_t d = base + 2 * A_BYTES + r * PITCH + c16 * 16;
            cp16(d,           sh);
            cp16(d + B_BYTES, sl);
        }
        asm volatile("cp.async.commit_group;" ::: "memory");
    };

    const int warp_m = (wid & 3) * 32;
    const int warp_n = (wid >> 2) * 32;

    float acc[2][4][4];
#pragma unroll
    for (int a = 0; a < 2; ++a)
#pragma unroll
        for (int b = 0; b < 4; ++b)
#pragma unroll
            for (int c = 0; c < 4; ++c) acc[a][b][c] = 0.f;

    load_chunk(0, 0);

    for (int ch = 0; ch < NCH; ++ch) {
        const int buf = ch & 1;
        if (ch + 1 < NCH) {
            load_chunk(buf ^ 1, ch + 1);
            asm volatile("cp.async.wait_group 1;" ::: "memory");
        } else {
            asm volatile("cp.async.wait_group 0;" ::: "memory");
        }
        __syncthreads();

        const uint32_t Ab = smb + buf * BUF_B;
        const uint32_t Bb = Ab + 2 * A_BYTES;
#pragma unroll
        for (int kk = 0; kk < 2; ++kk) {
            const int kc = kk * 16;
            uint32_t ah[2][4], al[2][4], bh[2][4], bl[2][4];
#pragma unroll
            for (int mi = 0; mi < 2; ++mi) {
                const int r = warp_m + mi * 16 + (lane & 7) + ((lane >> 3) & 1) * 8;
                const int c = kc + (lane >> 4) * 8;
                const uint32_t ad = Ab + r * PITCH + c * 2;
                ldm4(ah[mi], ad);
                ldm4(al[mi], ad + A_BYTES);
            }
#pragma unroll
            for (int gi = 0; gi < 2; ++gi) {
                const int r = warp_n + gi * 16 + ((lane >> 4) & 1) * 8 + (lane & 7);
                const int c = kc + ((lane >> 3) & 1) * 8;
                const uint32_t bd = Bb + r * PITCH + c * 2;
                ldm4(bh[gi], bd);
                ldm4(bl[gi], bd + B_BYTES);
            }
#pragma unroll
            for (int mi = 0; mi < 2; ++mi)
#pragma unroll
                for (int ni = 0; ni < 4; ++ni) {
                    const uint32_t* bhp = &bh[ni >> 1][(ni & 1) * 2];
                    const uint32_t* blp = &bl[ni >> 1][(ni & 1) * 2];
                    mma16816(acc[mi][ni], ah[mi], bhp);
                    mma16816(acc[mi][ni], ah[mi], blp);
                    mma16816(acc[mi][ni], al[mi], bhp);
                }
        }
        __syncthreads();
    }

    // ---------------- epilogue ----------------
#pragma unroll
    for (int mi = 0; mi < 2; ++mi)
#pragma unroll
        for (int ni = 0; ni < 4; ++ni)
#pragma unroll
            for (int half = 0; half < 2; ++half) {
                const int gm = row0 + warp_m + mi * 16 + (lane >> 2) + half * 8;
                const int gn = n0 + warp_n + ni * 8 + 2 * (lane & 3);
                float v0 = acc[mi][ni][half * 2 + 0];
                float v1 = acc[mi][ni][half * 2 + 1];
                if (MODE == 0) {
                    v0 = fmaxf(v0, 0.f); v1 = fmaxf(v1, 0.f);
                    const int b = gn >> 7, g = gn & 127;
                    *(float2*)(out + (((size_t)(b * 16 + targ)) * 1024 + gm) * 128 + g)
                        = make_float2(v0, v1);
                    __nv_bfloat16 h0, l0, h1, l1;
                    split2(v0, h0, l0); split2(v1, h1, l1);
                    const size_t ho = ((size_t)(b * 1024 + gm)) * 128 + g;
                    *(__nv_bfloat162*)(g_hh + ho) = __halves2bfloat162(h0, h1);
                    *(__nv_bfloat162*)(g_hl + ho) = __halves2bfloat162(l0, l1);
                } else if (MODE == 1) {
                    const int kk = gm >> 7, g = gm & 127;
                    const int b = gn >> 10, m = gn & 1023;
                    __nv_bfloat16 h0, l0, h1, l1;
                    split2(v0, h0, l0); split2(v1, h1, l1);
                    const size_t o = ((size_t)(b * 128 + g)) * 4096 + kk * 1024 + m;
                    *(__nv_bfloat162*)(g_Sth + o) = __halves2bfloat162(h0, h1);
                    *(__nv_bfloat162*)(g_Stl + o) = __halves2bfloat162(l0, l1);
                } else {
                    __nv_bfloat16 h0, l0, h1, l1;
                    split2(v0, h0, l0); split2(v1, h1, l1);
                    const size_t o = (size_t)gm * 4096 + targ * 1024 + gn;
                    *(__nv_bfloat162*)(g_Lh + o) = __halves2bfloat162(h0, h1);
                    *(__nv_bfloat162*)(g_Ll + o) = __halves2bfloat162(l0, l1);
                }
            }
}

// ---------------- prep kernels ----------------
__global__ void splitL0_k(const float* __restrict__ L)
{
    const int e = blockIdx.x * 256 + threadIdx.x;       // 1M
    const int r = e >> 10, c = e & 1023;
    __nv_bfloat16 h, l;
    split2(L[e], h, l);
    g_Lh[(size_t)r * 4096 + c] = h;
    g_Ll[(size_t)r * 4096 + c] = l;
}

__global__ void transLT_k(const float* __restrict__ L)
{
    __shared__ float tile[32][33];
    const int bx = blockIdx.x * 32, by = blockIdx.y * 32;
    const int x = threadIdx.x, y = threadIdx.y;          // block (32, 8)
#pragma unroll
    for (int i = 0; i < 32; i += 8)
        tile[y + i][x] = L[(size_t)(by + y + i) * 1024 + bx + x];
    __syncthreads();
#pragma unroll
    for (int i = 0; i < 32; i += 8) {
        __nv_bfloat16 h, l;
        split2(tile[x][y + i], h, l);                    // = L[by+x][bx+y+i]
        const size_t o = (size_t)(bx + y + i) * 1024 + by + x;
        g_LTh[o] = h;
        g_LTl[o] = l;
    }
}

__global__ void splitX_k(const float* __restrict__ x)
{
    const size_t e = ((size_t)blockIdx.x * 256 + threadIdx.x) * 4;
    const float4 v = *(const float4*)(x + e);
    __nv_bfloat16 h0, l0, h1, l1, h2, l2, h3, l3;
    split2(v.x, h0, l0); split2(v.y, h1, l1);
    split2(v.z, h2, l2); split2(v.w, h3, l3);
    *(__nv_bfloat162*)(g_xh + e)     = __halves2bfloat162(h0, h1);
    *(__nv_bfloat162*)(g_xh + e + 2) = __halves2bfloat162(h2, h3);
    *(__nv_bfloat162*)(g_xl + e)     = __halves2bfloat162(l0, l1);
    *(__nv_bfloat162*)(g_xl + e + 2) = __halves2bfloat162(l2, l3);
}

__global__ void catWHT_k(const float* __restrict__ W, const float* __restrict__ H)
{
    const int e = blockIdx.x * 256 + threadIdx.x;        // 512*256
    const int kg = e >> 8, f = e & 255;
    const int k = kg >> 7, g = kg & 127;
    const float v = (f < 128) ? W[k * 16384 + f * 128 + g]
                              : H[k * 16384 + (f - 128) * 128 + g];
    __nv_bfloat16 hi, lo;
    split2(v, hi, lo);
    g_WHTh[e] = hi;
    g_WHTl[e] = lo;
}

__global__ void zeroH_k()
{
    const size_t e = ((size_t)blockIdx.x * 256 + threadIdx.x) * 4;
    *(uint2*)(g_hh + e) = make_uint2(0u, 0u);
    *(uint2*)(g_hl + e) = make_uint2(0u, 0u);
}

// ---------------- launch ----------------
extern "C" void kernel_launch(void* const* d_in, const int* in_sizes, int n_in,
                              void* d_out, int out_size)
{
    const float* x = (const float*)d_in[0]; // [8,16,1024,128]
    const float* L = (const float*)d_in[1]; // [1024,1024]
    const float* W = (const float*)d_in[2]; // [4,128,128]
    const float* H = (const float*)d_in[3]; // [4,128,128]
    float* out = (float*)d_out;
    (void)in_sizes; (void)n_in; (void)out_size;

    cudaFuncSetAttribute(mma_k<0>, cudaFuncAttributeMaxDynamicSharedMemorySize, SMEM_TOT);
    cudaFuncSetAttribute(mma_k<1>, cudaFuncAttributeMaxDynamicSharedMemorySize, SMEM_TOT);
    cudaFuncSetAttribute(mma_k<2>, cudaFuncAttributeMaxDynamicSharedMemorySize, SMEM_TOT);

    splitL0_k<<<4096, 256>>>(L);
    transLT_k<<<dim3(32, 32), dim3(32, 8)>>>(L);
    catWHT_k <<<512, 256>>>(W, H);
    splitX_k <<<16384, 256>>>(x);
    zeroH_k  <<<1024, 256>>>();

    // L powers: slot s = slot (s-1) @ L   (bf16x3, writes hi/lo splits directly)
    for (int s = 1; s < 4; ++s)
        mma_k<2><<<dim3(16, 8), 256, SMEM_TOT>>>(nullptr, s);

    // recurrence
    for (int t = 0; t < 16; ++t) {
        mma_k<1><<<dim3(128, 4), 256, SMEM_TOT>>>(nullptr, t); // St = WHT @ [x_t|h]
        mma_k<0><<<dim3(16, 8),  256, SMEM_TOT>>>(out, t);     // z = Lcat @ St^T
    }
}

// round 7
// speedup vs baseline: 1.8052x; 1.0028x over previous
#include <cuda_runtime.h>
#include <cuda_bf16.h>
#include <cstdint>

// ============================================================================
// RGNN via warp-level mma.sync, bf16x3 split precision (sm_100-safe path).
//   h_t = relu( sum_k L^{k+1} (x_t W_k + h_{t-1} H_k) ), B=8,T=16,N=1024,F=128,K=4
//
// fp32 v = hi(bf16) + lo(bf16 residual); C ~= AhBh + AhBl + AlBh.
// bf16 (8-bit exponent) is REQUIRED: h grows ~2x/step to ~1e5 (fp16 overflows).
//
//   MODE 2 (powers):  Lslot[s] = Lslot[s-1] @ L^T-major     K=1024
//   MODE 1 (feature): St[(k,g)][(b,m)] = WHT @ [x_t|h]      K=256
//   MODE 0 (main):    z[m][(b,g)] = Lcat @ St^T             K=4096
// ============================================================================

// ---------------- device globals ----------------
__device__ __align__(256) __nv_bfloat16 g_Lh  [1024u * 4096u]; // L^1..L^4 hi [m][k]
__device__ __align__(256) __nv_bfloat16 g_Ll  [1024u * 4096u]; // lo
__device__ __align__(256) __nv_bfloat16 g_LTh [1024u * 1024u]; // L^T hi [n][k]
__device__ __align__(256) __nv_bfloat16 g_LTl [1024u * 1024u];
__device__ __align__(256) __nv_bfloat16 g_Sth [1024u * 4096u]; // St hi [(b,g)][(k,m)]
__device__ __align__(256) __nv_bfloat16 g_Stl [1024u * 4096u];
__device__ __align__(256) __nv_bfloat16 g_xh  [16777216u];     // x hi [b][t][n][f]
__device__ __align__(256) __nv_bfloat16 g_xl  [16777216u];
__device__ __align__(256) __nv_bfloat16 g_hh  [1048576u];      // h hi [(b*1024+n)][f]
__device__ __align__(256) __nv_bfloat16 g_hl  [1048576u];
__device__ __align__(256) __nv_bfloat16 g_WHTh[512u * 256u];   // WHT hi [(k*128+g)][f']
__device__ __align__(256) __nv_bfloat16 g_WHTl[512u * 256u];

// ---------------- helpers ----------------
__device__ __forceinline__ uint32_t smem_u32(const void* p) {
    uint32_t a;
    asm("{ .reg .u64 t; cvta.to.shared.u64 t, %1; cvt.u32.u64 %0, t; }"
        : "=r"(a) : "l"(p));
    return a;
}
__device__ __forceinline__ void cp16(uint32_t dst, const void* src) {
    asm volatile("cp.async.cg.shared.global [%0], [%1], 16;" :: "r"(dst), "l"(src));
}
__device__ __forceinline__ void ldm4(uint32_t* r, uint32_t a) {
    asm volatile("ldmatrix.sync.aligned.m8n8.x4.shared.b16 {%0,%1,%2,%3}, [%4];"
        : "=r"(r[0]), "=r"(r[1]), "=r"(r[2]), "=r"(r[3]) : "r"(a));
}
__device__ __forceinline__ void mma16816(float* d, const uint32_t* a, const uint32_t* b) {
    asm volatile(
        "mma.sync.aligned.m16n8k16.row.col.f32.bf16.bf16.f32 "
        "{%0,%1,%2,%3}, {%4,%5,%6,%7}, {%8,%9}, {%0,%1,%2,%3};"
        : "+f"(d[0]), "+f"(d[1]), "+f"(d[2]), "+f"(d[3])
        : "r"(a[0]), "r"(a[1]), "r"(a[2]), "r"(a[3]), "r"(b[0]), "r"(b[1]));
}
__device__ __forceinline__ void split2(float v, __nv_bfloat16& h, __nv_bfloat16& l) {
    h = __float2bfloat16(v);
    l = __float2bfloat16(v - __bfloat162float(h));
}

// ---------------- smem geometry ----------------
// 32 bf16 per row = 64B data + 16B pad -> pitch 80B (conflict-free ldmatrix rows)
static constexpr int PITCH    = 80;
static constexpr int A_BYTES  = 128 * PITCH;                 // 10240
static constexpr int B_BYTES  = 64 * PITCH;                  // 5120
static constexpr int STAGE_B  = 2 * A_BYTES + 2 * B_BYTES;   // 30720
static constexpr int SMEM_TOT = 3 * STAGE_B;                 // 92160 (3-stage ring)

// ============================================================================
// Unified GEMM kernel. CTA tile 128(m) x 64(n), 8 warps of 32x32, k-chunk 32.
// MODE 0: main (K=4096)  MODE 1: feature (K=256)  MODE 2: powers (K=1024)
// All modes: 3-term bf16 split (AhBh + AhBl + AlBh).
// ============================================================================
template<int MODE>
__global__ __launch_bounds__(256, 2)
void mma_k(float* __restrict__ out, const int targ)   // targ = t (0,1) or slot (2)
{
    extern __shared__ __align__(128) char sm[];
    const uint32_t smb = smem_u32(sm);
    const int tid  = threadIdx.x;
    const int wid  = tid >> 5, lane = tid & 31;
    const int row0 = blockIdx.y * 128;
    const int n0   = blockIdx.x * 64;

    constexpr int NCH = (MODE == 0) ? 128 : (MODE == 1 ? 8 : 32);

    const __nv_bfloat16 *Ah, *Al;
    int lda;
    if (MODE == 1) {
        Ah = g_WHTh + (size_t)row0 * 256; Al = g_WHTl + (size_t)row0 * 256; lda = 256;
    } else {
        const int kofs = (MODE == 2) ? (targ - 1) * 1024 : 0;
        Ah = g_Lh + (size_t)row0 * 4096 + kofs;
        Al = g_Ll + (size_t)row0 * 4096 + kofs;
        lda = 4096;
    }

    auto load_chunk = [&](int stage, int ch) {
        const int k0 = ch * 32;
        const uint32_t base = smb + stage * STAGE_B;
        // A: 128 rows x 32 bf16, hi+lo
#pragma unroll
        for (int i = 0; i < 2; ++i) {
            const int idx = i * 256 + tid;          // 0..511
            const int r = idx >> 2, c16 = idx & 3;
            const size_t o = (size_t)r * lda + k0 + c16 * 8;
            const uint32_t d = base + r * PITCH + c16 * 16;
            cp16(d,           Ah + o);
            cp16(d + A_BYTES, Al + o);
        }
        // B: 64 rows x 32 bf16, hi+lo
        {
            const int r = tid >> 2, c16 = tid & 3;
            const __nv_bfloat16 *sh, *sl;
            if (MODE == 0) {
                const size_t o = (size_t)(n0 + r) * 4096 + k0 + c16 * 8;
                sh = g_Sth + o; sl = g_Stl + o;
            } else if (MODE == 2) {
                const size_t o = (size_t)(n0 + r) * 1024 + k0 + c16 * 8;
                sh = g_LTh + o; sl = g_LTl + o;
            } else {
                const int j = n0 + r, b = j >> 10, m = j & 1023;
                if (k0 < 128) {
                    const size_t o = (((size_t)(b * 16 + targ)) * 1024 + m) * 128
                                   + k0 + c16 * 8;
                    sh = g_xh + o; sl = g_xl + o;
                } else {
                    const size_t o = ((size_t)(b * 1024 + m)) * 128
                                   + (k0 - 128) + c16 * 8;
                    sh = g_hh + o; sl = g_hl + o;
                }
            }
            const uint32_t d = base + 2 * A_BYTES + r * PITCH + c16 * 16;
            cp16(d,           sh);
            cp16(d + B_BYTES, sl);
        }
        asm volatile("cp.async.commit_group;" ::: "memory");
    };

    const int warp_m = (wid & 3) * 32;
    const int warp_n = (wid >> 2) * 32;

    float acc[2][4][4];
#pragma unroll
    for (int a = 0; a < 2; ++a)
#pragma unroll
        for (int b = 0; b < 4; ++b)
#pragma unroll
            for (int c = 0; c < 4; ++c) acc[a][b][c] = 0.f;

    // 3-stage pipeline, one __syncthreads per chunk
    load_chunk(0, 0);
    load_chunk(1, 1);

#pragma unroll 1
    for (int ch = 0; ch < NCH; ++ch) {
        if (ch + 1 < NCH)
            asm volatile("cp.async.wait_group 1;" ::: "memory");
        else
            asm volatile("cp.async.wait_group 0;" ::: "memory");
        __syncthreads();

        const int stage = ch % 3;
        const uint32_t Ab = smb + stage * STAGE_B;
        const uint32_t Bb = Ab + 2 * A_BYTES;
#pragma unroll
        for (int kk = 0; kk < 2; ++kk) {
            const int kc = kk * 16;
            uint32_t ah[2][4], al[2][4], bh[2][4], bl[2][4];
#pragma unroll
            for (int mi = 0; mi < 2; ++mi) {
                const int r = warp_m + mi * 16 + (lane & 7) + ((lane >> 3) & 1) * 8;
                const int c = kc + (lane >> 4) * 8;
                const uint32_t ad = Ab + r * PITCH + c * 2;
                ldm4(ah[mi], ad);
                ldm4(al[mi], ad + A_BYTES);
            }
#pragma unroll
            for (int gi = 0; gi < 2; ++gi) {
                const int r = warp_n + gi * 16 + ((lane >> 4) & 1) * 8 + (lane & 7);
                const int c = kc + ((lane >> 3) & 1) * 8;
                const uint32_t bd = Bb + r * PITCH + c * 2;
                ldm4(bh[gi], bd);
                ldm4(bl[gi], bd + B_BYTES);
            }
#pragma unroll
            for (int mi = 0; mi < 2; ++mi)
#pragma unroll
                for (int ni = 0; ni < 4; ++ni) {
                    const uint32_t* bhp = &bh[ni >> 1][(ni & 1) * 2];
                    const uint32_t* blp = &bl[ni >> 1][(ni & 1) * 2];
                    mma16816(acc[mi][ni], ah[mi], bhp);
                    mma16816(acc[mi][ni], ah[mi], blp);
                    mma16816(acc[mi][ni], al[mi], bhp);
                }
        }
        if (ch + 2 < NCH)
            load_chunk((ch + 2) % 3, ch + 2);
        else
            asm volatile("cp.async.commit_group;" ::: "memory"); // keep group count
    }

    // ---------------- epilogue ----------------
#pragma unroll
    for (int mi = 0; mi < 2; ++mi)
#pragma unroll
        for (int ni = 0; ni < 4; ++ni)
#pragma unroll
            for (int half = 0; half < 2; ++half) {
                const int gm = row0 + warp_m + mi * 16 + (lane >> 2) + half * 8;
                const int gn = n0 + warp_n + ni * 8 + 2 * (lane & 3);
                float v0 = acc[mi][ni][half * 2 + 0];
                float v1 = acc[mi][ni][half * 2 + 1];
                if (MODE == 0) {
                    v0 = fmaxf(v0, 0.f); v1 = fmaxf(v1, 0.f);
                    const int b = gn >> 7, g = gn & 127;
                    *(float2*)(out + (((size_t)(b * 16 + targ)) * 1024 + gm) * 128 + g)
                        = make_float2(v0, v1);
                    __nv_bfloat16 h0, l0, h1, l1;
                    split2(v0, h0, l0); split2(v1, h1, l1);
                    const size_t ho = ((size_t)(b * 1024 + gm)) * 128 + g;
                    *(__nv_bfloat162*)(g_hh + ho) = __halves2bfloat162(h0, h1);
                    *(__nv_bfloat162*)(g_hl + ho) = __halves2bfloat162(l0, l1);
                } else if (MODE == 1) {
                    const int kk = gm >> 7, g = gm & 127;
                    const int b = gn >> 10, m = gn & 1023;
                    __nv_bfloat16 h0, l0, h1, l1;
                    split2(v0, h0, l0); split2(v1, h1, l1);
                    const size_t o = ((size_t)(b * 128 + g)) * 4096 + kk * 1024 + m;
                    *(__nv_bfloat162*)(g_Sth + o) = __halves2bfloat162(h0, h1);
                    *(__nv_bfloat162*)(g_Stl + o) = __halves2bfloat162(l0, l1);
                } else {
                    __nv_bfloat16 h0, l0, h1, l1;
                    split2(v0, h0, l0); split2(v1, h1, l1);
                    const size_t o = (size_t)gm * 4096 + targ * 1024 + gn;
                    *(__nv_bfloat162*)(g_Lh + o) = __halves2bfloat162(h0, h1);
                    *(__nv_bfloat162*)(g_Ll + o) = __halves2bfloat162(l0, l1);
                }
            }
}

// ---------------- prep kernels ----------------
__global__ void splitL0_k(const float* __restrict__ L)
{
    const int e = blockIdx.x * 256 + threadIdx.x;       // 1M
    const int r = e >> 10, c = e & 1023;
    __nv_bfloat16 h, l;
    split2(L[e], h, l);
    g_Lh[(size_t)r * 4096 + c] = h;
    g_Ll[(size_t)r * 4096 + c] = l;
}

__global__ void transLT_k(const float* __restrict__ L)
{
    __shared__ float tile[32][33];
    const int bx = blockIdx.x * 32, by = blockIdx.y * 32;
    const int x = threadIdx.x, y = threadIdx.y;          // block (32, 8)
#pragma unroll
    for (int i = 0; i < 32; i += 8)
        tile[y + i][x] = L[(size_t)(by + y + i) * 1024 + bx + x];
    __syncthreads();
#pragma unroll
    for (int i = 0; i < 32; i += 8) {
        __nv_bfloat16 h, l;
        split2(tile[x][y + i], h, l);                    // = L[by+x][bx+y+i]
        const size_t o = (size_t)(bx + y + i) * 1024 + by + x;
        g_LTh[o] = h;
        g_LTl[o] = l;
    }
}

__global__ void splitX_k(const float* __restrict__ x)
{
    const size_t e = ((size_t)blockIdx.x * 256 + threadIdx.x) * 4;
    const float4 v = *(const float4*)(x + e);
    __nv_bfloat16 h0, l0, h1, l1, h2, l2, h3, l3;
    split2(v.x, h0, l0); split2(v.y, h1, l1);
    split2(v.z, h2, l2); split2(v.w, h3, l3);
    *(__nv_bfloat162*)(g_xh + e)     = __halves2bfloat162(h0, h1);
    *(__nv_bfloat162*)(g_xh + e + 2) = __halves2bfloat162(h2, h3);
    *(__nv_bfloat162*)(g_xl + e)     = __halves2bfloat162(l0, l1);
    *(__nv_bfloat162*)(g_xl + e + 2) = __halves2bfloat162(l2, l3);
}

__global__ void catWHT_k(const float* __restrict__ W, const float* __restrict__ H)
{
    const int e = blockIdx.x * 256 + threadIdx.x;        // 512*256
    const int kg = e >> 8, f = e & 255;
    const int k = kg >> 7, g = kg & 127;
    const float v = (f < 128) ? W[k * 16384 + f * 128 + g]
                              : H[k * 16384 + (f - 128) * 128 + g];
    __nv_bfloat16 hi, lo;
    split2(v, hi, lo);
    g_WHTh[e] = hi;
    g_WHTl[e] = lo;
}

__global__ void zeroH_k()
{
    const size_t e = ((size_t)blockIdx.x * 256 + threadIdx.x) * 4;
    *(uint2*)(g_hh + e) = make_uint2(0u, 0u);
    *(uint2*)(g_hl + e) = make_uint2(0u, 0u);
}

// ---------------- launch ----------------
extern "C" void kernel_launch(void* const* d_in, const int* in_sizes, int n_in,
                              void* d_out, int out_size)
{
    const float* x = (const float*)d_in[0]; // [8,16,1024,128]
    const float* L = (const float*)d_in[1]; // [1024,1024]
    const float* W = (const float*)d_in[2]; // [4,128,128]
    const float* H = (const float*)d_in[3]; // [4,128,128]
    float* out = (float*)d_out;
    (void)in_sizes; (void)n_in; (void)out_size;

    cudaFuncSetAttribute(mma_k<0>, cudaFuncAttributeMaxDynamicSharedMemorySize, SMEM_TOT);
    cudaFuncSetAttribute(mma_k<1>, cudaFuncAttributeMaxDynamicSharedMemorySize, SMEM_TOT);
    cudaFuncSetAttribute(mma_k<2>, cudaFuncAttributeMaxDynamicSharedMemorySize, SMEM_TOT);

    // Order keeps an MMA kernel at profiled-launch index 3 (power GEMM).
    splitL0_k<<<4096, 256>>>(L);                           // 0
    transLT_k<<<dim3(32, 32), dim3(32, 8)>>>(L);           // 1
    for (int s = 1; s < 4; ++s)                            // 2,3,4
        mma_k<2><<<dim3(16, 8), 256, SMEM_TOT>>>(nullptr, s);
    catWHT_k <<<512, 256>>>(W, H);                         // 5
    splitX_k <<<16384, 256>>>(x);                          // 6
    zeroH_k  <<<1024, 256>>>();                            // 7

    for (int t = 0; t < 16; ++t) {
        mma_k<1><<<dim3(128, 4), 256, SMEM_TOT>>>(nullptr, t); // St = WHT @ [x_t|h]
        mma_k<0><<<dim3(16, 8),  256, SMEM_TOT>>>(out, t);     // z = Lcat @ St^T
    }
}

// round 8
// speedup vs baseline: 1.8722x; 1.0371x over previous
#include <cuda_runtime.h>
#include <cuda_bf16.h>
#include <cstdint>

// ============================================================================
// RGNN via warp-level mma.sync, bf16x3 split precision (sm_100-safe path).
//   h_t = relu( sum_k L^{k+1} (x_t W_k + h_{t-1} H_k) ), B=8,T=16,N=1024,F=128,K=4
//
// R7: 64x64 CTA tile / 4 warps / 128 threads, grid >= 256 CTAs (was 128 CTAs
// on 148 SMs -> occ 12%, tensor 37%); 4-stage cp.async ring (prefetch 3).
//
//   MODE 2 (powers):  Lslot[s] = Lslot[s-1] @ L^T-major     K=1024, grid 16x16
//   MODE 1 (feature): St[(k,g)][(b,m)] = WHT @ [x_t|h]      K=256,  grid 128x8
//   MODE 0 (main):    z[m][(b,g)] = Lcat @ St^T             K=4096, grid 16x16
// ============================================================================

// ---------------- device globals ----------------
__device__ __align__(256) __nv_bfloat16 g_Lh  [1024u * 4096u]; // L^1..L^4 hi [m][k]
__device__ __align__(256) __nv_bfloat16 g_Ll  [1024u * 4096u]; // lo
__device__ __align__(256) __nv_bfloat16 g_LTh [1024u * 1024u]; // L^T hi [n][k]
__device__ __align__(256) __nv_bfloat16 g_LTl [1024u * 1024u];
__device__ __align__(256) __nv_bfloat16 g_Sth [1024u * 4096u]; // St hi [(b,g)][(k,m)]
__device__ __align__(256) __nv_bfloat16 g_Stl [1024u * 4096u];
__device__ __align__(256) __nv_bfloat16 g_xh  [16777216u];     // x hi [b][t][n][f]
__device__ __align__(256) __nv_bfloat16 g_xl  [16777216u];
__device__ __align__(256) __nv_bfloat16 g_hh  [1048576u];      // h hi [(b*1024+n)][f]
__device__ __align__(256) __nv_bfloat16 g_hl  [1048576u];
__device__ __align__(256) __nv_bfloat16 g_WHTh[512u * 256u];   // WHT hi [(k*128+g)][f']
__device__ __align__(256) __nv_bfloat16 g_WHTl[512u * 256u];

// ---------------- helpers ----------------
__device__ __forceinline__ uint32_t smem_u32(const void* p) {
    uint32_t a;
    asm("{ .reg .u64 t; cvta.to.shared.u64 t, %1; cvt.u32.u64 %0, t; }"
        : "=r"(a) : "l"(p));
    return a;
}
__device__ __forceinline__ void cp16(uint32_t dst, const void* src) {
    asm volatile("cp.async.cg.shared.global [%0], [%1], 16;" :: "r"(dst), "l"(src));
}
__device__ __forceinline__ void ldm4(uint32_t* r, uint32_t a) {
    asm volatile("ldmatrix.sync.aligned.m8n8.x4.shared.b16 {%0,%1,%2,%3}, [%4];"
        : "=r"(r[0]), "=r"(r[1]), "=r"(r[2]), "=r"(r[3]) : "r"(a));
}
__device__ __forceinline__ void mma16816(float* d, const uint32_t* a, const uint32_t* b) {
    asm volatile(
        "mma.sync.aligned.m16n8k16.row.col.f32.bf16.bf16.f32 "
        "{%0,%1,%2,%3}, {%4,%5,%6,%7}, {%8,%9}, {%0,%1,%2,%3};"
        : "+f"(d[0]), "+f"(d[1]), "+f"(d[2]), "+f"(d[3])
        : "r"(a[0]), "r"(a[1]), "r"(a[2]), "r"(a[3]), "r"(b[0]), "r"(b[1]));
}
__device__ __forceinline__ void split2(float v, __nv_bfloat16& h, __nv_bfloat16& l) {
    h = __float2bfloat16(v);
    l = __float2bfloat16(v - __bfloat162float(h));
}

// ---------------- smem geometry ----------------
// 32 bf16 per row = 64B data + 16B pad -> pitch 80B (conflict-free ldmatrix rows)
static constexpr int PITCH    = 80;
static constexpr int TILE_B   = 64 * PITCH;       // 5120 (64 rows x 32 bf16)
static constexpr int STAGE_B  = 4 * TILE_B;       // Ah, Al, Bh, Bl = 20480
static constexpr int STAGES   = 4;
static constexpr int SMEM_TOT = STAGES * STAGE_B; // 81920

// ============================================================================
// Unified GEMM kernel. CTA tile 64(m) x 64(n), 4 warps of 32x32, k-chunk 32.
// 4-stage cp.async ring, prefetch distance 3, one __syncthreads per chunk.
// All modes: 3-term bf16 split (AhBh + AhBl + AlBh).
// ============================================================================
template<int MODE>
__global__ __launch_bounds__(128, 2)
void mma_k(float* __restrict__ out, const int targ)   // targ = t (0,1) or slot (2)
{
    extern __shared__ __align__(128) char sm[];
    const uint32_t smb = smem_u32(sm);
    const int tid  = threadIdx.x;
    const int wid  = tid >> 5, lane = tid & 31;
    const int row0 = blockIdx.y * 64;
    const int n0   = blockIdx.x * 64;

    constexpr int NCH = (MODE == 0) ? 128 : (MODE == 1 ? 8 : 32);

    const __nv_bfloat16 *Ah, *Al;
    int lda;
    if (MODE == 1) {
        Ah = g_WHTh + (size_t)row0 * 256; Al = g_WHTl + (size_t)row0 * 256; lda = 256;
    } else {
        const int kofs = (MODE == 2) ? (targ - 1) * 1024 : 0;
        Ah = g_Lh + (size_t)row0 * 4096 + kofs;
        Al = g_Ll + (size_t)row0 * 4096 + kofs;
        lda = 4096;
    }

    auto load_chunk = [&](int stage, int ch) {
        const int k0 = ch * 32;
        const uint32_t base = smb + stage * STAGE_B;
        // A: 64 rows x 32 bf16, hi+lo  (256 cp16 per component, 128 threads)
#pragma unroll
        for (int i = 0; i < 2; ++i) {
            const int idx = i * 128 + tid;          // 0..255
            const int r = idx >> 2, c16 = idx & 3;
            const size_t o = (size_t)r * lda + k0 + c16 * 8;
            const uint32_t d = base + r * PITCH + c16 * 16;
            cp16(d,          Ah + o);
            cp16(d + TILE_B, Al + o);
        }
        // B: 64 rows x 32 bf16, hi+lo
#pragma unroll
        for (int i = 0; i < 2; ++i) {
            const int idx = i * 128 + tid;
            const int r = idx >> 2, c16 = idx & 3;
            const __nv_bfloat16 *sh, *sl;
            if (MODE == 0) {
                const size_t o = (size_t)(n0 + r) * 4096 + k0 + c16 * 8;
                sh = g_Sth + o; sl = g_Stl + o;
            } else if (MODE == 2) {
                const size_t o = (size_t)(n0 + r) * 1024 + k0 + c16 * 8;
                sh = g_LTh + o; sl = g_LTl + o;
            } else {
                const int j = n0 + r, b = j >> 10, m = j & 1023;
                if (k0 < 128) {
                    const size_t o = (((size_t)(b * 16 + targ)) * 1024 + m) * 128
                                   + k0 + c16 * 8;
                    sh = g_xh + o; sl = g_xl + o;
                } else {
                    const size_t o = ((size_t)(b * 1024 + m)) * 128
                                   + (k0 - 128) + c16 * 8;
                    sh = g_hh + o; sl = g_hl + o;
                }
            }
            const uint32_t d = base + 2 * TILE_B + r * PITCH + c16 * 16;
            cp16(d,          sh);
            cp16(d + TILE_B, sl);
        }
        asm volatile("cp.async.commit_group;" ::: "memory");
    };

    const int warp_m = (wid & 1) * 32;
    const int warp_n = (wid >> 1) * 32;

    float acc[2][4][4];
#pragma unroll
    for (int a = 0; a < 2; ++a)
#pragma unroll
        for (int b = 0; b < 4; ++b)
#pragma unroll
            for (int c = 0; c < 4; ++c) acc[a][b][c] = 0.f;

    // prefetch 3 chunks (NCH >= 8 in all modes)
    load_chunk(0, 0);
    load_chunk(1, 1);
    load_chunk(2, 2);

#pragma unroll 1
    for (int ch = 0; ch < NCH; ++ch) {
        if (ch + 3 <= NCH)
            asm volatile("cp.async.wait_group 2;" ::: "memory");
        else if (ch + 2 == NCH)
            asm volatile("cp.async.wait_group 1;" ::: "memory");
        else
            asm volatile("cp.async.wait_group 0;" ::: "memory");
        __syncthreads();

        const int stage = ch & 3;
        const uint32_t Ab = smb + stage * STAGE_B;
        const uint32_t Bb = Ab + 2 * TILE_B;
#pragma unroll
        for (int kk = 0; kk < 2; ++kk) {
            const int kc = kk * 16;
            uint32_t ah[2][4], al[2][4], bh[2][4], bl[2][4];
#pragma unroll
            for (int mi = 0; mi < 2; ++mi) {
                const int r = warp_m + mi * 16 + (lane & 7) + ((lane >> 3) & 1) * 8;
                const int c = kc + (lane >> 4) * 8;
                const uint32_t ad = Ab + r * PITCH + c * 2;
                ldm4(ah[mi], ad);
                ldm4(al[mi], ad + TILE_B);
            }
#pragma unroll
            for (int gi = 0; gi < 2; ++gi) {
                const int r = warp_n + gi * 16 + ((lane >> 4) & 1) * 8 + (lane & 7);
                const int c = kc + ((lane >> 3) & 1) * 8;
                const uint32_t bd = Bb + r * PITCH + c * 2;
                ldm4(bh[gi], bd);
                ldm4(bl[gi], bd + TILE_B);
            }
#pragma unroll
            for (int mi = 0; mi < 2; ++mi)
#pragma unroll
                for (int ni = 0; ni < 4; ++ni) {
                    const uint32_t* bhp = &bh[ni >> 1][(ni & 1) * 2];
                    const uint32_t* blp = &bl[ni >> 1][(ni & 1) * 2];
                    mma16816(acc[mi][ni], ah[mi], bhp);
                    mma16816(acc[mi][ni], ah[mi], blp);
                    mma16816(acc[mi][ni], al[mi], bhp);
                }
        }
        if (ch + 3 < NCH)
            load_chunk((ch + 3) & 3, ch + 3);
    }

    // ---------------- epilogue ----------------
#pragma unroll
    for (int mi = 0; mi < 2; ++mi)
#pragma unroll
        for (int ni = 0; ni < 4; ++ni)
#pragma unroll
            for (int half = 0; half < 2; ++half) {
                const int gm = row0 + warp_m + mi * 16 + (lane >> 2) + half * 8;
                const int gn = n0 + warp_n + ni * 8 + 2 * (lane & 3);
                float v0 = acc[mi][ni][half * 2 + 0];
                float v1 = acc[mi][ni][half * 2 + 1];
                if (MODE == 0) {
                    v0 = fmaxf(v0, 0.f); v1 = fmaxf(v1, 0.f);
                    const int b = gn >> 7, g = gn & 127;
                    *(float2*)(out + (((size_t)(b * 16 + targ)) * 1024 + gm) * 128 + g)
                        = make_float2(v0, v1);
                    __nv_bfloat16 h0, l0, h1, l1;
                    split2(v0, h0, l0); split2(v1, h1, l1);
                    const size_t ho = ((size_t)(b * 1024 + gm)) * 128 + g;
                    *(__nv_bfloat162*)(g_hh + ho) = __halves2bfloat162(h0, h1);
                    *(__nv_bfloat162*)(g_hl + ho) = __halves2bfloat162(l0, l1);
                } else if (MODE == 1) {
                    const int kk = gm >> 7, g = gm & 127;
                    const int b = gn >> 10, m = gn & 1023;
                    __nv_bfloat16 h0, l0, h1, l1;
                    split2(v0, h0, l0); split2(v1, h1, l1);
                    const size_t o = ((size_t)(b * 128 + g)) * 4096 + kk * 1024 + m;
                    *(__nv_bfloat162*)(g_Sth + o) = __halves2bfloat162(h0, h1);
                    *(__nv_bfloat162*)(g_Stl + o) = __halves2bfloat162(l0, l1);
                } else {
                    __nv_bfloat16 h0, l0, h1, l1;
                    split2(v0, h0, l0); split2(v1, h1, l1);
                    const size_t o = (size_t)gm * 4096 + targ * 1024 + gn;
                    *(__nv_bfloat162*)(g_Lh + o) = __halves2bfloat162(h0, h1);
                    *(__nv_bfloat162*)(g_Ll + o) = __halves2bfloat162(l0, l1);
                }
            }
}

// ---------------- prep kernels ----------------
__global__ void splitL0_k(const float* __restrict__ L)
{
    const int e = blockIdx.x * 256 + threadIdx.x;       // 1M
    const int r = e >> 10, c = e & 1023;
    __nv_bfloat16 h, l;
    split2(L[e], h, l);
    g_Lh[(size_t)r * 4096 + c] = h;
    g_Ll[(size_t)r * 4096 + c] = l;
}

__global__ void transLT_k(const float* __restrict__ L)
{
    __shared__ float tile[32][33];
    const int bx = blockIdx.x * 32, by = blockIdx.y * 32;
    const int x = threadIdx.x, y = threadIdx.y;          // block (32, 8)
#pragma unroll
    for (int i = 0; i < 32; i += 8)
        tile[y + i][x] = L[(size_t)(by + y + i) * 1024 + bx + x];
    __syncthreads();
#pragma unroll
    for (int i = 0; i < 32; i += 8) {
        __nv_bfloat16 h, l;
        split2(tile[x][y + i], h, l);                    // = L[by+x][bx+y+i]
        const size_t o = (size_t)(bx + y + i) * 1024 + by + x;
        g_LTh[o] = h;
        g_LTl[o] = l;
    }
}

__global__ void splitX_k(const float* __restrict__ x)
{
    const size_t e = ((size_t)blockIdx.x * 256 + threadIdx.x) * 4;
    const float4 v = *(const float4*)(x + e);
    __nv_bfloat16 h0, l0, h1, l1, h2, l2, h3, l3;
    split2(v.x, h0, l0); split2(v.y, h1, l1);
    split2(v.z, h2, l2); split2(v.w, h3, l3);
    *(__nv_bfloat162*)(g_xh + e)     = __halves2bfloat162(h0, h1);
    *(__nv_bfloat162*)(g_xh + e + 2) = __halves2bfloat162(h2, h3);
    *(__nv_bfloat162*)(g_xl + e)     = __halves2bfloat162(l0, l1);
    *(__nv_bfloat162*)(g_xl + e + 2) = __halves2bfloat162(l2, l3);
}

__global__ void catWHT_k(const float* __restrict__ W, const float* __restrict__ H)
{
    const int e = blockIdx.x * 256 + threadIdx.x;        // 512*256
    const int kg = e >> 8, f = e & 255;
    const int k = kg >> 7, g = kg & 127;
    const float v = (f < 128) ? W[k * 16384 + f * 128 + g]
                              : H[k * 16384 + (f - 128) * 128 + g];
    __nv_bfloat16 hi, lo;
    split2(v, hi, lo);
    g_WHTh[e] = hi;
    g_WHTl[e] = lo;
}

__global__ void zeroH_k()
{
    const size_t e = ((size_t)blockIdx.x * 256 + threadIdx.x) * 4;
    *(uint2*)(g_hh + e) = make_uint2(0u, 0u);
    *(uint2*)(g_hl + e) = make_uint2(0u, 0u);
}

// ---------------- launch ----------------
extern "C" void kernel_launch(void* const* d_in, const int* in_sizes, int n_in,
                              void* d_out, int out_size)
{
    const float* x = (const float*)d_in[0]; // [8,16,1024,128]
    const float* L = (const float*)d_in[1]; // [1024,1024]
    const float* W = (const float*)d_in[2]; // [4,128,128]
    const float* H = (const float*)d_in[3]; // [4,128,128]
    float* out = (float*)d_out;
    (void)in_sizes; (void)n_in; (void)out_size;

    cudaFuncSetAttribute(mma_k<0>, cudaFuncAttributeMaxDynamicSharedMemorySize, SMEM_TOT);
    cudaFuncSetAttribute(mma_k<1>, cudaFuncAttributeMaxDynamicSharedMemorySize, SMEM_TOT);
    cudaFuncSetAttribute(mma_k<2>, cudaFuncAttributeMaxDynamicSharedMemorySize, SMEM_TOT);

    // Order keeps an MMA kernel at profiled-launch index 3 (power GEMM).
    splitL0_k<<<4096, 256>>>(L);                           // 0
    transLT_k<<<dim3(32, 32), dim3(32, 8)>>>(L);           // 1
    for (int s = 1; s < 4; ++s)                            // 2,3,4
        mma_k<2><<<dim3(16, 16), 128, SMEM_TOT>>>(nullptr, s);
    catWHT_k <<<512, 256>>>(W, H);                         // 5
    splitX_k <<<16384, 256>>>(x);                          // 6
    zeroH_k  <<<1024, 256>>>();                            // 7

    for (int t = 0; t < 16; ++t) {
        mma_k<1><<<dim3(128, 8), 128, SMEM_TOT>>>(nullptr, t); // St = WHT @ [x_t|h]
        mma_k<0><<<dim3(16, 16), 128, SMEM_TOT>>>(out, t);     // z = Lcat @ St^T
    }
}